// round 4
// baseline (speedup 1.0000x reference)
#include <cuda_runtime.h>

#define GX 1024
#define GY 1024
#define GZ 40
#define NCELLS (GX * GY * GZ)
#define MAXV 60000
#define MAXP 32
#define SLOTS (MAXV * MAXP)
#define BLK 256
#define IPT 4
#define TILE (BLK * IPT)
#define NMAX 1250000
#define NTMAX ((NMAX + TILE - 1) / TILE + 8)

// Scratch (zero-initialized; every call restores all-zero state -> graph replays identical)
__device__ int      g_map[NCELLS];    // 0 empty; >0 claim key (n-i of first pt); <0 -(vid+1)
__device__ int      g_flat[NMAX];     // flat cell id per point, -1 invalid (fully overwritten)
__device__ unsigned g_status[NTMAX];  // lookback: 0 | 0x4000_0000|agg | 0x8000_0000|inclusive
__device__ int      g_voxelNum;
__device__ unsigned g_slots[SLOTS];   // 0 empty, else key = n - point_idx
__device__ int      g_cnt[MAXV];
__device__ int      g_coors[MAXV * 3];

// ---------------------------------------------------------------------------
// A: coords -> flat id, atomicMax claim of first point (key n-i; 0 stays empty)
// ---------------------------------------------------------------------------
__global__ void kA_claim(const float4* __restrict__ pts, int n) {
    int base = blockIdx.x * TILE;
    #pragma unroll
    for (int k = 0; k < IPT; k++) {
        int i = base + k * BLK + threadIdx.x;
        if (i >= n) break;
        float4 p = pts[i];
        // exact mirror of reference f32 math: floor((p - rmin) / vs)
        int cx = (int)floorf((p.x - (-51.2f)) / 0.1f);
        int cy = (int)floorf((p.y - (-51.2f)) / 0.1f);
        int cz = (int)floorf((p.z - (-5.0f)) / 0.2f);
        int flat = -1;
        if ((unsigned)cx < GX && (unsigned)cy < GY && (unsigned)cz < GZ) {
            flat = (cx * GY + cy) * GZ + cz;
            atomicMax(&g_map[flat], n - i);
        }
        g_flat[i] = flat;
    }
}

// ---------------------------------------------------------------------------
// B: rep flags -> decoupled-lookback scan -> vid assignment, map retag, coors.
// No point-insertion here: the map is only CONSUMED by kC after this kernel
// finishes, so no inter-block spin on g_map is needed.
// Rep detection is race-free: a cell read by tile T can only be retagged by a
// tile <= T (the rep has the minimum point index); seeing either the claim
// key or the retag value yields the same rep decision.
// ---------------------------------------------------------------------------
__global__ void kB_scan_assign(int n, int nTiles) {
    const int tid = threadIdx.x;
    const int lane = tid & 31, wid = tid >> 5;
    const int tile = blockIdx.x;
    const int base = tile * TILE;

    __shared__ int s_warp[BLK / 32];
    __shared__ int s_wexcl[BLK / 32];
    __shared__ int s_run;
    __shared__ int s_excl;

    if (tid == 0) s_run = 0;

    // front-batched loads (flat coalesced; map random -> MLP 4)
    int flat[IPT];
    int mval[IPT];
    #pragma unroll
    for (int k = 0; k < IPT; k++) {
        int i = base + k * BLK + tid;
        int f = -1, v = 0;
        if (i < n) {
            f = g_flat[i];
            if (f >= 0) v = __ldcg(&g_map[f]);
        }
        flat[k] = f;
        mval[k] = v;
    }
    __syncthreads();

    // per-slice block scan of rep flags (slices in point-index order)
    int rep[IPT], localPos[IPT];
    #pragma unroll
    for (int k = 0; k < IPT; k++) {
        int i = base + k * BLK + tid;
        int r = (flat[k] >= 0 && mval[k] == n - i) ? 1 : 0;
        rep[k] = r;
        unsigned m = __ballot_sync(0xffffffffu, r);
        int lanePre = __popc(m & ((1u << lane) - 1u));
        if (lane == 0) s_warp[wid] = __popc(m);
        __syncthreads();
        if (tid == 0) {
            int acc = s_run;
            #pragma unroll
            for (int w = 0; w < BLK / 32; w++) { int t = s_warp[w]; s_wexcl[w] = acc; acc += t; }
            s_run = acc;
        }
        __syncthreads();
        localPos[k] = s_wexcl[wid] + lanePre;
    }
    int agg = s_run;

    // publish aggregate, warp-parallel lookback (volatile: no CSE, word-atomic payload)
    volatile unsigned* vst = g_status;
    if (wid == 0) {
        if (lane == 0) vst[tile] = 0x40000000u | (unsigned)agg;
        unsigned excl = 0;
        int j = tile - 1;
        while (j >= 0) {
            int idx = j - lane;
            unsigned w;
            if (idx >= 0) {
                do { w = vst[idx]; } while (w == 0u);
            } else {
                w = 0x80000000u;  // virtual prefix 0 before tile 0
            }
            unsigned isPre = __ballot_sync(0xffffffffu, (w & 0x80000000u) != 0u);
            if (isPre) {
                int pl = __ffs(isPre) - 1;  // nearest tile carrying an inclusive prefix
                unsigned contrib = (lane <= pl) ? (w & 0x3FFFFFFFu) : 0u;
                #pragma unroll
                for (int o = 16; o; o >>= 1) contrib += __shfl_down_sync(0xffffffffu, contrib, o);
                if (lane == 0) excl += contrib;
                break;
            } else {
                unsigned contrib = w & 0x3FFFFFFFu;
                #pragma unroll
                for (int o = 16; o; o >>= 1) contrib += __shfl_down_sync(0xffffffffu, contrib, o);
                if (lane == 0) excl += contrib;
                j -= 32;
            }
        }
        if (lane == 0) {
            s_excl = (int)excl;
            vst[tile] = 0x80000000u | (excl + (unsigned)agg);
            if (tile == nTiles - 1) {
                int tot = (int)(excl + (unsigned)agg);
                g_voxelNum = tot < MAXV ? tot : MAXV;
            }
        }
    }
    __syncthreads();
    int excl = s_excl;

    // retag ALL rep cells with -(vid+1); coors for kept voxels
    #pragma unroll
    for (int k = 0; k < IPT; k++) {
        if (rep[k]) {
            int vid = excl + localPos[k];
            int f = flat[k];
            __stcg(&g_map[f], -(vid + 1));
            if (vid < MAXV) {
                g_coors[vid * 3 + 0] = f % GZ;
                g_coors[vid * 3 + 1] = (f / GZ) % GY;
                g_coors[vid * 3 + 2] = f / (GZ * GY);
            }
        }
    }
}

// ---------------------------------------------------------------------------
// C: insertion against the FINALIZED map (every valid cell is < 0 now).
// Deterministic atomicMax ripple: final state = 32 smallest point indices,
// sorted ascending, independent of thread interleaving.
// ---------------------------------------------------------------------------
__global__ void kC_insert(int n) {
    int base = blockIdx.x * TILE;
    int flat[IPT];
    #pragma unroll
    for (int k = 0; k < IPT; k++) {
        int i = base + k * BLK + threadIdx.x;
        flat[k] = (i < n) ? g_flat[i] : -1;
    }
    int mval[IPT];
    #pragma unroll
    for (int k = 0; k < IPT; k++)
        mval[k] = (flat[k] >= 0) ? __ldcg(&g_map[flat[k]]) : 0;

    #pragma unroll
    for (int k = 0; k < IPT; k++) {
        int v = mval[k];
        if (v >= 0) continue;          // invalid point (or impossible untagged cell)
        int vid = -v - 1;
        if (vid >= MAXV) continue;     // voxel beyond cap: dropped
        atomicAdd(&g_cnt[vid], 1);
        int i = base + k * BLK + threadIdx.x;
        unsigned key = (unsigned)(n - i);
        unsigned* sl = &g_slots[(unsigned)vid * MAXP];
        for (int s = 0; s < MAXP; s++) {
            unsigned old = atomicMax(&sl[s], key);
            if (old < key) {
                if (old == 0u) break;  // landed in empty slot
                key = old;             // displaced occupant ripples right
            }
        }
    }
}

// ---------------------------------------------------------------------------
// D: split-range — [0,SLOTS): emit outputs + reset slots/cnt;
//    [SLOTS, SLOTS+n): scattered map clean + lookback-status reset.
// Output layout: voxels[60000*32*4] | coors[60000*3] | npv[60000] | voxel_num[1]
// ---------------------------------------------------------------------------
__global__ void kD_emit_clean(const float4* __restrict__ pts, float* __restrict__ out,
                              int n, int nTiles) {
    int idx = blockIdx.x * BLK + threadIdx.x;
    if (idx < SLOTS) {
        int vid = idx >> 5, s = idx & 31;
        unsigned k = g_slots[idx];
        float4 val = make_float4(0.f, 0.f, 0.f, 0.f);
        if (k) {
            g_slots[idx] = 0;
            val = pts[n - (int)k];
        }
        reinterpret_cast<float4*>(out)[idx] = val;
        if (s == 0) {
            int c = g_cnt[vid];
            if (c) g_cnt[vid] = 0;
            if (c > MAXP) c = MAXP;
            const int OC = SLOTS * 4;
            const int ON = OC + MAXV * 3;
            out[ON + vid] = (float)c;
            int vn = g_voxelNum;
            float cz = 0.f, cy = 0.f, cx = 0.f;
            if (vid < vn) {
                cz = (float)g_coors[vid * 3 + 0];
                cy = (float)g_coors[vid * 3 + 1];
                cx = (float)g_coors[vid * 3 + 2];
            }
            out[OC + vid * 3 + 0] = cz;
            out[OC + vid * 3 + 1] = cy;
            out[OC + vid * 3 + 2] = cx;
            if (idx == 0) out[ON + MAXV] = (float)vn;
        }
    } else {
        int j = idx - SLOTS;
        if (j < n) {
            int f = g_flat[j];
            if (f >= 0) g_map[f] = 0;
        }
        if (j < nTiles) g_status[j] = 0;
    }
}

extern "C" void kernel_launch(void* const* d_in, const int* in_sizes, int n_in,
                              void* d_out, int out_size) {
    const float4* pts = (const float4*)d_in[0];
    int n = in_sizes[0] / 4;
    float* out = (float*)d_out;
    int nT = (n + TILE - 1) / TILE;

    kA_claim<<<nT, BLK>>>(pts, n);
    kB_scan_assign<<<nT, BLK>>>(n, nT);
    kC_insert<<<nT, BLK>>>(n);
    kD_emit_clean<<<(SLOTS + n + BLK - 1) / BLK, BLK>>>(pts, out, n, nT);
}

// round 5
// speedup vs baseline: 1.1041x; 1.1041x over previous
#include <cuda_runtime.h>

#define GX 1024
#define GY 1024
#define GZ 40
#define NCELLS (GX * GY * GZ)
#define MAXV 60000
#define MAXP 32
#define SLOTS (MAXV * MAXP)
#define BLK 256
#define IPT 4
#define TILE (BLK * IPT)
#define NMAX 1250000
#define NTMAX ((NMAX + TILE - 1) / TILE + 8)
#define PV_RESOLVED 0x40000000

// Scratch. Zero-initialized once at module load. The 64-bit map is NEVER
// cleaned: cells carry a generation tag; stale generations parse as empty and
// lose every atomicMax against current-gen keys. All other state is either
// fully overwritten each call or reset by kD -> graph replays are identical.
__device__ unsigned long long g_map[NCELLS]; // (gen<<32) | (n-i) claim key; gen mismatch = empty
__device__ unsigned g_gen;                   // bumped by kD at end of each call
__device__ int      g_flat[NMAX];            // flat cell id per point, -1 invalid
__device__ int      g_pvid[NMAX];            // -1 invalid | PV_RESOLVED|vid (rep) | i_rep (non-rep)
__device__ unsigned g_status[NTMAX];         // lookback: 0 | 0x4000_0000|agg | 0x8000_0000|incl
__device__ int      g_voxelNum;
__device__ unsigned g_slots[SLOTS];          // 0 empty, else key = n - point_idx (cleared by kD)
__device__ int      g_cnt[MAXV];             // cleared by kD
__device__ int      g_coors[MAXV * 3];       // only [0,voxel_num) read each call

// ---------------------------------------------------------------------------
// A: coords -> flat id, gen-tagged atomicMax claim of first point.
// ---------------------------------------------------------------------------
__global__ void kA_claim(const float4* __restrict__ pts, int n) {
    unsigned gen = __ldcg(&g_gen) + 1u;
    int base = blockIdx.x * TILE;
    #pragma unroll
    for (int k = 0; k < IPT; k++) {
        int i = base + k * BLK + threadIdx.x;
        if (i >= n) break;
        float4 p = pts[i];
        // exact mirror of reference f32 math: floor((p - rmin) / vs)
        int cx = (int)floorf((p.x - (-51.2f)) / 0.1f);
        int cy = (int)floorf((p.y - (-51.2f)) / 0.1f);
        int cz = (int)floorf((p.z - (-5.0f)) / 0.2f);
        int flat = -1;
        if ((unsigned)cx < GX && (unsigned)cy < GY && (unsigned)cz < GZ) {
            flat = (cx * GY + cy) * GZ + cz;
            unsigned long long key = ((unsigned long long)gen << 32) | (unsigned)(n - i);
            atomicMax(&g_map[flat], key);
        }
        g_flat[i] = flat;
    }
}

// ---------------------------------------------------------------------------
// B: single map read per point -> rep flags -> decoupled-lookback scan ->
// vid assignment, coors, and per-point resolution table g_pvid.
// No map writes at all. Claims are final (kA completed), so the read is
// race-free; non-reps learn their rep's point index from the claim key.
// ---------------------------------------------------------------------------
__global__ void kB_scan_assign(int n, int nTiles) {
    const int tid = threadIdx.x;
    const int lane = tid & 31, wid = tid >> 5;
    const int tile = blockIdx.x;
    const int base = tile * TILE;
    const unsigned gen = __ldcg(&g_gen) + 1u;

    __shared__ int s_warp[BLK / 32];
    __shared__ int s_wexcl[BLK / 32];
    __shared__ int s_run;
    __shared__ int s_excl;

    if (tid == 0) s_run = 0;

    // front-batched loads (flat coalesced; map random -> MLP 4)
    int flat[IPT];
    int key[IPT];  // claim key (n - i_rep) or 0 if cell empty/stale-gen
    #pragma unroll
    for (int k = 0; k < IPT; k++) {
        int i = base + k * BLK + tid;
        int f = -1, kk = 0;
        if (i < n) {
            f = g_flat[i];
            if (f >= 0) {
                unsigned long long cell = __ldcg(&g_map[f]);
                if ((unsigned)(cell >> 32) == gen) kk = (int)(unsigned)cell;
            }
        }
        flat[k] = f;
        key[k] = kk;
    }
    __syncthreads();

    // per-slice block scan of rep flags (slices in point-index order)
    int rep[IPT], localPos[IPT];
    #pragma unroll
    for (int k = 0; k < IPT; k++) {
        int i = base + k * BLK + tid;
        int r = (flat[k] >= 0 && key[k] == n - i) ? 1 : 0;
        rep[k] = r;
        unsigned m = __ballot_sync(0xffffffffu, r);
        int lanePre = __popc(m & ((1u << lane) - 1u));
        if (lane == 0) s_warp[wid] = __popc(m);
        __syncthreads();
        if (tid == 0) {
            int acc = s_run;
            #pragma unroll
            for (int w = 0; w < BLK / 32; w++) { int t = s_warp[w]; s_wexcl[w] = acc; acc += t; }
            s_run = acc;
        }
        __syncthreads();
        localPos[k] = s_wexcl[wid] + lanePre;
    }
    int agg = s_run;

    // publish aggregate, warp-parallel lookback (volatile — proven in R4)
    volatile unsigned* vst = g_status;
    if (wid == 0) {
        if (lane == 0) vst[tile] = 0x40000000u | (unsigned)agg;
        unsigned excl = 0;
        int j = tile - 1;
        while (j >= 0) {
            int idx = j - lane;
            unsigned w;
            if (idx >= 0) {
                do { w = vst[idx]; } while (w == 0u);
            } else {
                w = 0x80000000u;  // virtual prefix 0 before tile 0
            }
            unsigned isPre = __ballot_sync(0xffffffffu, (w & 0x80000000u) != 0u);
            if (isPre) {
                int pl = __ffs(isPre) - 1;
                unsigned contrib = (lane <= pl) ? (w & 0x3FFFFFFFu) : 0u;
                #pragma unroll
                for (int o = 16; o; o >>= 1) contrib += __shfl_down_sync(0xffffffffu, contrib, o);
                if (lane == 0) excl += contrib;
                break;
            } else {
                unsigned contrib = w & 0x3FFFFFFFu;
                #pragma unroll
                for (int o = 16; o; o >>= 1) contrib += __shfl_down_sync(0xffffffffu, contrib, o);
                if (lane == 0) excl += contrib;
                j -= 32;
            }
        }
        if (lane == 0) {
            s_excl = (int)excl;
            vst[tile] = 0x80000000u | (excl + (unsigned)agg);
            if (tile == nTiles - 1) {
                int tot = (int)(excl + (unsigned)agg);
                g_voxelNum = tot < MAXV ? tot : MAXV;
            }
        }
    }
    __syncthreads();
    int excl = s_excl;

    // emit coors (reps with vid < MAXV) and the per-point resolution table
    #pragma unroll
    for (int k = 0; k < IPT; k++) {
        int i = base + k * BLK + tid;
        if (i >= n) break;
        int out;
        if (flat[k] < 0) {
            out = -1;
        } else if (rep[k]) {
            int vid = excl + localPos[k];
            out = PV_RESOLVED | vid;
            if (vid < MAXV) {
                int f = flat[k];
                g_coors[vid * 3 + 0] = f % GZ;
                g_coors[vid * 3 + 1] = (f / GZ) % GY;
                g_coors[vid * 3 + 2] = f / (GZ * GY);
            }
        } else {
            out = n - key[k];  // rep's point index (claim is final -> key > 0)
        }
        g_pvid[i] = out;
    }
}

// ---------------------------------------------------------------------------
// C: resolve vid via the small L2-resident g_pvid table; deterministic
// atomicMax ripple insertion (final = 32 smallest indices, sorted).
// ---------------------------------------------------------------------------
__global__ void kC_insert(int n) {
    int base = blockIdx.x * TILE;
    int v[IPT];
    #pragma unroll
    for (int k = 0; k < IPT; k++) {
        int i = base + k * BLK + threadIdx.x;
        v[k] = (i < n) ? g_pvid[i] : -1;
    }
    #pragma unroll
    for (int k = 0; k < IPT; k++) {
        if (v[k] < 0) continue;
        int r = v[k];
        if (!(r & PV_RESOLVED)) r = __ldcg(&g_pvid[r]);  // rep entry is always resolved
        int vid = r & (PV_RESOLVED - 1);
        if (vid >= MAXV) continue;  // voxel beyond cap: dropped
        atomicAdd(&g_cnt[vid], 1);
        int i = base + k * BLK + threadIdx.x;
        unsigned key = (unsigned)(n - i);
        unsigned* sl = &g_slots[(unsigned)vid * MAXP];
        for (int s = 0; s < MAXP; s++) {
            unsigned old = atomicMax(&sl[s], key);
            if (old < key) {
                if (old == 0u) break;  // landed in empty slot
                key = old;             // displaced occupant ripples right
            }
        }
    }
}

// ---------------------------------------------------------------------------
// D: emit outputs + reset slots/cnt; tail range clears lookback status and
// bumps the generation for the next call. No map traffic at all.
// Output layout: voxels[60000*32*4] | coors[60000*3] | npv[60000] | voxel_num[1]
// ---------------------------------------------------------------------------
__global__ void kD_emit(const float4* __restrict__ pts, float* __restrict__ out,
                        int n, int nTiles) {
    int idx = blockIdx.x * BLK + threadIdx.x;
    if (idx < SLOTS) {
        int vid = idx >> 5, s = idx & 31;
        unsigned k = g_slots[idx];
        float4 val = make_float4(0.f, 0.f, 0.f, 0.f);
        if (k) {
            g_slots[idx] = 0;
            val = pts[n - (int)k];
        }
        reinterpret_cast<float4*>(out)[idx] = val;
        if (s == 0) {
            int c = g_cnt[vid];
            if (c) g_cnt[vid] = 0;
            if (c > MAXP) c = MAXP;
            const int OC = SLOTS * 4;
            const int ON = OC + MAXV * 3;
            out[ON + vid] = (float)c;
            int vn = g_voxelNum;
            float cz = 0.f, cy = 0.f, cx = 0.f;
            if (vid < vn) {
                cz = (float)g_coors[vid * 3 + 0];
                cy = (float)g_coors[vid * 3 + 1];
                cx = (float)g_coors[vid * 3 + 2];
            }
            out[OC + vid * 3 + 0] = cz;
            out[OC + vid * 3 + 1] = cy;
            out[OC + vid * 3 + 2] = cx;
            if (idx == 0) out[ON + MAXV] = (float)vn;
        }
    } else {
        int j = idx - SLOTS;
        if (j < nTiles) g_status[j] = 0;
        if (j == nTiles) g_gen = g_gen + 1u;  // next call / replay uses gen+1
    }
}

extern "C" void kernel_launch(void* const* d_in, const int* in_sizes, int n_in,
                              void* d_out, int out_size) {
    const float4* pts = (const float4*)d_in[0];
    int n = in_sizes[0] / 4;
    float* out = (float*)d_out;
    int nT = (n + TILE - 1) / TILE;

    kA_claim<<<nT, BLK>>>(pts, n);
    kB_scan_assign<<<nT, BLK>>>(n, nT);
    kC_insert<<<nT, BLK>>>(n);
    kD_emit<<<(SLOTS + nT + 1 + BLK - 1) / BLK, BLK>>>(pts, out, n, nT);
}

// round 6
// speedup vs baseline: 1.1950x; 1.0823x over previous
#include <cuda_runtime.h>

#define GX 1024
#define GY 1024
#define GZ 40
#define MAXV 60000
#define MAXP 32
#define SLOTS (MAXV * MAXP)
#define BLK 256
#define IPT 4
#define TILE (BLK * IPT)
#define NMAX 1250000
#define NTMAX ((NMAX + TILE - 1) / TILE + 8)
#define PV_RESOLVED 0x40000000

// L2-resident open-addressing hash table. Entry (64-bit):
//   0 = empty; else ((flat+1) << 21) | key, key = n - i  (21 bits: n < 2^21).
// Slot ownership is claimed once by atomicCAS(0 -> entry); after that all
// contenders for the same flat share identical high bits, so atomicMax on the
// packed word == per-voxel max over keys (first-point claim). One slot per
// flat per call (CAS only succeeds on 0; entries never change owner).
#define HBITS 21
#define HSIZE (1u << HBITS)
#define HMASK (HSIZE - 1u)

__device__ __align__(16) unsigned long long g_htab[HSIZE];  // zeroed by kD each call
__device__ int      g_flat[NMAX];     // flat cell id per point, -1 invalid (fully overwritten)
__device__ int      g_pvid[NMAX];     // -1 | PV_RESOLVED|vid (rep) | i_rep (non-rep)
__device__ unsigned g_status[NTMAX];  // lookback: 0 | 0x4000_0000|agg | 0x8000_0000|incl
__device__ int      g_voxelNum;
__device__ unsigned g_slots[SLOTS];   // 0 empty, else key = n - point_idx (cleared by kD)
__device__ int      g_cnt[MAXV];      // cleared by kD
__device__ int      g_coors[MAXV * 3];

__device__ __forceinline__ unsigned hslot(int flat) {
    return (unsigned)(((unsigned long long)(unsigned)flat * 0x9E3779B97F4A7C15ull) >> (64 - HBITS));
}

// ---------------------------------------------------------------------------
// A: coords -> flat id; hash-claim + packed atomicMax (all L2-resident).
// ---------------------------------------------------------------------------
__global__ void kA_claim(const float4* __restrict__ pts, int n) {
    int base = blockIdx.x * TILE;
    #pragma unroll
    for (int k = 0; k < IPT; k++) {
        int i = base + k * BLK + threadIdx.x;
        if (i >= n) break;
        float4 p = pts[i];
        // exact mirror of reference f32 math: floor((p - rmin) / vs)
        int cx = (int)floorf((p.x - (-51.2f)) / 0.1f);
        int cy = (int)floorf((p.y - (-51.2f)) / 0.1f);
        int cz = (int)floorf((p.z - (-5.0f)) / 0.2f);
        int flat = -1;
        if ((unsigned)cx < GX && (unsigned)cy < GY && (unsigned)cz < GZ) {
            flat = (cx * GY + cy) * GZ + cz;
            unsigned long long pref = ((unsigned long long)(unsigned)(flat + 1)) << 21;
            unsigned long long ent = pref | (unsigned)(n - i);
            unsigned s = hslot(flat);
            for (;;) {
                unsigned long long cur = __ldcg(&g_htab[s]);
                if ((cur >> 21) == (pref >> 21)) { atomicMax(&g_htab[s], ent); break; }
                if (cur == 0ull) {
                    unsigned long long old = atomicCAS(&g_htab[s], 0ull, ent);
                    if (old == 0ull) break;                                   // claimed
                    if ((old >> 21) == (pref >> 21)) { atomicMax(&g_htab[s], ent); break; }
                    // other flat won this slot: keep probing
                }
                s = (s + 1) & HMASK;
            }
        }
        g_flat[i] = flat;
    }
}

// ---------------------------------------------------------------------------
// B: hash lookup (L2 hits) -> rep flags -> decoupled-lookback scan -> vid,
// coors, per-point resolution table g_pvid. Claims final (kA done): race-free.
// ---------------------------------------------------------------------------
__global__ void kB_scan_assign(int n, int nTiles) {
    const int tid = threadIdx.x;
    const int lane = tid & 31, wid = tid >> 5;
    const int tile = blockIdx.x;
    const int base = tile * TILE;

    __shared__ int s_warp[BLK / 32];
    __shared__ int s_wexcl[BLK / 32];
    __shared__ int s_run;
    __shared__ int s_excl;

    if (tid == 0) s_run = 0;

    // front-batched: flat loads + first hash probe (MLP), then rare fix-ups
    int flat[IPT];
    unsigned hs[IPT];
    unsigned long long cell[IPT];
    #pragma unroll
    for (int k = 0; k < IPT; k++) {
        int i = base + k * BLK + tid;
        int f = (i < n) ? g_flat[i] : -1;
        flat[k] = f;
        hs[k] = (f >= 0) ? hslot(f) : 0u;
        cell[k] = (f >= 0) ? __ldcg(&g_htab[hs[k]]) : 0ull;
    }
    int key[IPT];  // claim key (n - i_rep), or 0 for invalid points
    #pragma unroll
    for (int k = 0; k < IPT; k++) {
        int kk = 0;
        if (flat[k] >= 0) {
            unsigned long long want = ((unsigned long long)(unsigned)(flat[k] + 1));
            unsigned s = hs[k];
            unsigned long long cur = cell[k];
            while ((cur >> 21) != want) {     // guaranteed to terminate: entry exists
                s = (s + 1) & HMASK;
                cur = __ldcg(&g_htab[s]);
            }
            kk = (int)(cur & 0x1FFFFFull);
        }
        key[k] = kk;
    }
    __syncthreads();

    // per-slice block scan of rep flags (slices in point-index order)
    int rep[IPT], localPos[IPT];
    #pragma unroll
    for (int k = 0; k < IPT; k++) {
        int i = base + k * BLK + tid;
        int r = (flat[k] >= 0 && key[k] == n - i) ? 1 : 0;
        rep[k] = r;
        unsigned m = __ballot_sync(0xffffffffu, r);
        int lanePre = __popc(m & ((1u << lane) - 1u));
        if (lane == 0) s_warp[wid] = __popc(m);
        __syncthreads();
        if (tid == 0) {
            int acc = s_run;
            #pragma unroll
            for (int w = 0; w < BLK / 32; w++) { int t = s_warp[w]; s_wexcl[w] = acc; acc += t; }
            s_run = acc;
        }
        __syncthreads();
        localPos[k] = s_wexcl[wid] + lanePre;
    }
    int agg = s_run;

    // publish aggregate, warp-parallel lookback (volatile — proven R4/R5)
    volatile unsigned* vst = g_status;
    if (wid == 0) {
        if (lane == 0) vst[tile] = 0x40000000u | (unsigned)agg;
        unsigned excl = 0;
        int j = tile - 1;
        while (j >= 0) {
            int idx = j - lane;
            unsigned w;
            if (idx >= 0) {
                do { w = vst[idx]; } while (w == 0u);
            } else {
                w = 0x80000000u;  // virtual prefix 0 before tile 0
            }
            unsigned isPre = __ballot_sync(0xffffffffu, (w & 0x80000000u) != 0u);
            if (isPre) {
                int pl = __ffs(isPre) - 1;
                unsigned contrib = (lane <= pl) ? (w & 0x3FFFFFFFu) : 0u;
                #pragma unroll
                for (int o = 16; o; o >>= 1) contrib += __shfl_down_sync(0xffffffffu, contrib, o);
                if (lane == 0) excl += contrib;
                break;
            } else {
                unsigned contrib = w & 0x3FFFFFFFu;
                #pragma unroll
                for (int o = 16; o; o >>= 1) contrib += __shfl_down_sync(0xffffffffu, contrib, o);
                if (lane == 0) excl += contrib;
                j -= 32;
            }
        }
        if (lane == 0) {
            s_excl = (int)excl;
            vst[tile] = 0x80000000u | (excl + (unsigned)agg);
            if (tile == nTiles - 1) {
                int tot = (int)(excl + (unsigned)agg);
                g_voxelNum = tot < MAXV ? tot : MAXV;
            }
        }
    }
    __syncthreads();
    int excl = s_excl;

    // emit coors (reps with vid < MAXV) and the per-point resolution table
    #pragma unroll
    for (int k = 0; k < IPT; k++) {
        int i = base + k * BLK + tid;
        if (i >= n) break;
        int out;
        if (flat[k] < 0) {
            out = -1;
        } else if (rep[k]) {
            int vid = excl + localPos[k];
            out = PV_RESOLVED | vid;
            if (vid < MAXV) {
                int f = flat[k];
                g_coors[vid * 3 + 0] = f % GZ;
                g_coors[vid * 3 + 1] = (f / GZ) % GY;
                g_coors[vid * 3 + 2] = f / (GZ * GY);
            }
        } else {
            out = n - key[k];  // rep's point index
        }
        g_pvid[i] = out;
    }
}

// ---------------------------------------------------------------------------
// C: resolve vid via L2-resident g_pvid; deterministic atomicMax ripple
// insertion (final = 32 smallest indices, sorted ascending).
// ---------------------------------------------------------------------------
__global__ void kC_insert(int n) {
    int base = blockIdx.x * TILE;
    int v[IPT];
    #pragma unroll
    for (int k = 0; k < IPT; k++) {
        int i = base + k * BLK + threadIdx.x;
        v[k] = (i < n) ? g_pvid[i] : -1;
    }
    #pragma unroll
    for (int k = 0; k < IPT; k++) {
        if (v[k] < 0) continue;
        int r = v[k];
        if (!(r & PV_RESOLVED)) r = __ldcg(&g_pvid[r]);  // rep entry is always resolved
        int vid = r & (PV_RESOLVED - 1);
        if (vid >= MAXV) continue;  // voxel beyond cap: dropped
        atomicAdd(&g_cnt[vid], 1);
        int i = base + k * BLK + threadIdx.x;
        unsigned key = (unsigned)(n - i);
        unsigned* sl = &g_slots[(unsigned)vid * MAXP];
        for (int s = 0; s < MAXP; s++) {
            unsigned old = atomicMax(&sl[s], key);
            if (old < key) {
                if (old == 0u) break;  // landed in empty slot
                key = old;             // displaced occupant ripples right
            }
        }
    }
}

// ---------------------------------------------------------------------------
// D: emit outputs + reset slots/cnt; stream-zero the hash table (coalesced
// 16-byte stores); clear lookback status.
// Output layout: voxels[60000*32*4] | coors[60000*3] | npv[60000] | voxel_num[1]
// ---------------------------------------------------------------------------
__global__ void kD_emit(const float4* __restrict__ pts, float* __restrict__ out,
                        int n, int nTiles) {
    int idx = blockIdx.x * BLK + threadIdx.x;
    if (idx < SLOTS) {
        int vid = idx >> 5, s = idx & 31;
        unsigned k = g_slots[idx];
        float4 val = make_float4(0.f, 0.f, 0.f, 0.f);
        if (k) {
            g_slots[idx] = 0;
            val = pts[n - (int)k];
        }
        reinterpret_cast<float4*>(out)[idx] = val;
        if (s == 0) {
            int c = g_cnt[vid];
            if (c) g_cnt[vid] = 0;
            if (c > MAXP) c = MAXP;
            const int OC = SLOTS * 4;
            const int ON = OC + MAXV * 3;
            out[ON + vid] = (float)c;
            int vn = g_voxelNum;
            float cz = 0.f, cy = 0.f, cx = 0.f;
            if (vid < vn) {
                cz = (float)g_coors[vid * 3 + 0];
                cy = (float)g_coors[vid * 3 + 1];
                cx = (float)g_coors[vid * 3 + 2];
            }
            out[OC + vid * 3 + 0] = cz;
            out[OC + vid * 3 + 1] = cy;
            out[OC + vid * 3 + 2] = cx;
            if (idx == 0) out[ON + MAXV] = (float)vn;
        }
    } else {
        int j = idx - SLOTS;
        if (j < (int)(HSIZE / 2)) {
            // coalesced 16B stores: zero two hash entries per thread
            reinterpret_cast<ulonglong2*>(g_htab)[j] = make_ulonglong2(0ull, 0ull);
        } else {
            int j2 = j - (int)(HSIZE / 2);
            if (j2 < nTiles) g_status[j2] = 0;
        }
    }
}

extern "C" void kernel_launch(void* const* d_in, const int* in_sizes, int n_in,
                              void* d_out, int out_size) {
    const float4* pts = (const float4*)d_in[0];
    int n = in_sizes[0] / 4;
    float* out = (float*)d_out;
    int nT = (n + TILE - 1) / TILE;

    kA_claim<<<nT, BLK>>>(pts, n);
    kB_scan_assign<<<nT, BLK>>>(n, nT);
    kC_insert<<<nT, BLK>>>(n);
    kD_emit<<<(SLOTS + (int)(HSIZE / 2) + nT + BLK - 1) / BLK, BLK>>>(pts, out, n, nT);
}